// round 1
// baseline (speedup 1.0000x reference)
#include <cuda_runtime.h>

#define L_SEQ 2048
#define BATCH 2
#define EMB   256
#define NH    8
#define HD    32
#define NROWS (L_SEQ*BATCH)   // 4096
#define SCALE 0.17677669529663687f  // 32^-0.5

// Scratch (allocation-free): Q/K/V in [b][h][l][d] layout, attention out in [l][b][e]
__device__ float g_Q[BATCH*NH*L_SEQ*HD];
__device__ float g_K[BATCH*NH*L_SEQ*HD];
__device__ float g_V[BATCH*NH*L_SEQ*HD];
__device__ float g_AO[NROWS*EMB];

// ---------------------------------------------------------------------------
// Projection GEMM: C[4096,256] = X[4096,256] @ W[256,256] + bias
// SRC_AO: 0 = read X from param, 1 = read from g_AO
// DST: 0 = row-major to Cout param, 1/2/3 = scatter to g_Q/g_K/g_V ([b,h,l,d])
// ---------------------------------------------------------------------------
template<int SRC_AO, int DST>
__global__ __launch_bounds__(256) void proj_kernel(
    const float* __restrict__ Xin, const float* __restrict__ W,
    const float* __restrict__ bias, float* __restrict__ Cout)
{
    __shared__ float As[64][17];   // [m][k]
    __shared__ float Bs[16][65];   // [k][n]
    const float* __restrict__ X = SRC_AO ? (const float*)g_AO : Xin;

    int tid = threadIdx.x;
    int tx = tid & 15, ty = tid >> 4;
    int rowBase = blockIdx.y * 64;
    int colBase = blockIdx.x * 64;

    float acc[4][4];
    #pragma unroll
    for (int i = 0; i < 4; i++)
        #pragma unroll
        for (int j = 0; j < 4; j++) acc[i][j] = 0.f;

    for (int k0 = 0; k0 < EMB; k0 += 16) {
        #pragma unroll
        for (int i = 0; i < 4; i++) {
            int idx = tid + i * 256;
            int r = idx >> 4, kk = idx & 15;
            As[r][kk] = X[(rowBase + r) * EMB + k0 + kk];
        }
        #pragma unroll
        for (int i = 0; i < 4; i++) {
            int idx = tid + i * 256;
            int kk = idx >> 6, c = idx & 63;
            Bs[kk][c] = W[(k0 + kk) * EMB + colBase + c];
        }
        __syncthreads();
        #pragma unroll
        for (int kk = 0; kk < 16; kk++) {
            float a[4], b[4];
            #pragma unroll
            for (int i = 0; i < 4; i++) a[i] = As[ty * 4 + i][kk];
            #pragma unroll
            for (int j = 0; j < 4; j++) b[j] = Bs[kk][tx * 4 + j];
            #pragma unroll
            for (int i = 0; i < 4; i++)
                #pragma unroll
                for (int j = 0; j < 4; j++)
                    acc[i][j] = fmaf(a[i], b[j], acc[i][j]);
        }
        __syncthreads();
    }

    #pragma unroll
    for (int i = 0; i < 4; i++) {
        int r = rowBase + ty * 4 + i;
        #pragma unroll
        for (int j = 0; j < 4; j++) {
            int c = colBase + tx * 4 + j;
            float v = acc[i][j] + bias[c];
            if (DST == 0) {
                Cout[r * EMB + c] = v;
            } else {
                float* dst = (DST == 1) ? g_Q : (DST == 2) ? g_K : g_V;
                int l = r >> 1, b = r & 1;     // row = l*B + b
                int h = c >> 5, d = c & 31;    // col = h*HD + d
                dst[(((b * NH + h) * L_SEQ) + l) * HD + d] = v;
            }
        }
    }
}

// ---------------------------------------------------------------------------
// Flash attention: one CTA = one (b,h) x 64-query tile, loop 64-key tiles.
// Online softmax; Q pre-scaled by SCALE at load.
// ---------------------------------------------------------------------------
__global__ __launch_bounds__(128) void attn_kernel()
{
    __shared__ float Qt[64][33];    // [q][d], Q*SCALE
    __shared__ float Kts[32][65];   // [d][k]  (transposed for conflict-free QK reads)
    __shared__ float Vt[64][33];    // [k][d]
    __shared__ float Ps[64][65];    // probs tile
    __shared__ float m_s[64], l_s[64], alpha_s[64];

    int bh = blockIdx.y;            // b*NH + h
    int q0 = blockIdx.x * 64;
    const float* __restrict__ Qp = g_Q + (size_t)bh * (L_SEQ * HD);
    const float* __restrict__ Kp = g_K + (size_t)bh * (L_SEQ * HD);
    const float* __restrict__ Vp = g_V + (size_t)bh * (L_SEQ * HD);

    int tid = threadIdx.x;
    for (int i = tid; i < 64 * 32; i += 128) {
        int r = i >> 5, d = i & 31;
        Qt[r][d] = Qp[(q0 + r) * HD + d] * SCALE;
    }
    if (tid < 64) { m_s[tid] = -1e30f; l_s[tid] = 0.f; }

    int txq = tid & 15, tyq = tid >> 4;   // QK map: 8 rows x 4 cols per thread
    int txp = tid & 7,  typ = tid >> 3;   // PV map: 4 rows x 4 d-cols per thread

    float o[4][4];
    #pragma unroll
    for (int i = 0; i < 4; i++)
        #pragma unroll
        for (int j = 0; j < 4; j++) o[i][j] = 0.f;

    for (int kt = 0; kt < L_SEQ; kt += 64) {
        __syncthreads();   // protects Kts/Vt/Ps reuse + first-iter init
        for (int i = tid; i < 64 * 32; i += 128) {
            int r = i >> 5, d = i & 31;
            float kv = Kp[(kt + r) * HD + d];
            Kts[d][r] = kv;
            Vt[r][d] = Vp[(kt + r) * HD + d];
        }
        __syncthreads();

        // ---- S = Q K^T (scaled) ----
        float s[8][4];
        #pragma unroll
        for (int i = 0; i < 8; i++)
            #pragma unroll
            for (int j = 0; j < 4; j++) s[i][j] = 0.f;
        #pragma unroll
        for (int k = 0; k < 32; k++) {
            float qv[8], kv[4];
            #pragma unroll
            for (int i = 0; i < 8; i++) qv[i] = Qt[tyq * 8 + i][k];
            #pragma unroll
            for (int j = 0; j < 4; j++) kv[j] = Kts[k][txq * 4 + j];
            #pragma unroll
            for (int i = 0; i < 8; i++)
                #pragma unroll
                for (int j = 0; j < 4; j++)
                    s[i][j] = fmaf(qv[i], kv[j], s[i][j]);
        }

        // ---- online softmax (row stats shared across 16 txq lanes) ----
        #pragma unroll
        for (int i = 0; i < 8; i++) {
            int r = tyq * 8 + i;
            float mx = fmaxf(fmaxf(s[i][0], s[i][1]), fmaxf(s[i][2], s[i][3]));
            #pragma unroll
            for (int off = 8; off >= 1; off >>= 1)
                mx = fmaxf(mx, __shfl_xor_sync(0xffffffffu, mx, off, 16));
            float mold = m_s[r];
            float mnew = fmaxf(mold, mx);
            float psum = 0.f;
            #pragma unroll
            for (int j = 0; j < 4; j++) {
                float p = __expf(s[i][j] - mnew);
                Ps[r][txq * 4 + j] = p;
                psum += p;
            }
            #pragma unroll
            for (int off = 8; off >= 1; off >>= 1)
                psum += __shfl_xor_sync(0xffffffffu, psum, off, 16);
            // all lanes have read m_s[r]/reached the shfl barrier before this write
            if (txq == 0) {
                float alpha = __expf(mold - mnew);
                l_s[r] = l_s[r] * alpha + psum;
                m_s[r] = mnew;
                alpha_s[r] = alpha;
            }
        }
        __syncthreads();

        // ---- O = O*alpha + P V ----
        #pragma unroll
        for (int i = 0; i < 4; i++) {
            float a = alpha_s[typ * 4 + i];
            #pragma unroll
            for (int j = 0; j < 4; j++) o[i][j] *= a;
        }
        #pragma unroll 8
        for (int c = 0; c < 64; c++) {
            float vv[4];
            #pragma unroll
            for (int j = 0; j < 4; j++) vv[j] = Vt[c][txp * 4 + j];
            #pragma unroll
            for (int i = 0; i < 4; i++) {
                float p = Ps[typ * 4 + i][c];
                #pragma unroll
                for (int j = 0; j < 4; j++)
                    o[i][j] = fmaf(p, vv[j], o[i][j]);
            }
        }
    }

    // ---- normalize + store to g_AO [l, b, e] ----
    int b = bh >> 3, h = bh & 7;
    #pragma unroll
    for (int i = 0; i < 4; i++) {
        int r = typ * 4 + i;
        float inv = 1.f / l_s[r];
        int l = q0 + r;
        #pragma unroll
        for (int j = 0; j < 4; j++) {
            g_AO[(l * BATCH + b) * EMB + h * HD + txp * 4 + j] = o[i][j] * inv;
        }
    }
}

// ---------------------------------------------------------------------------
extern "C" void kernel_launch(void* const* d_in, const int* in_sizes, int n_in,
                              void* d_out, int out_size)
{
    const float* query = (const float*)d_in[0];
    const float* key_  = (const float*)d_in[1];
    const float* value = (const float*)d_in[2];
    const float* Wq = (const float*)d_in[3];
    const float* bq = (const float*)d_in[4];
    const float* Wk = (const float*)d_in[5];
    const float* bk = (const float*)d_in[6];
    const float* Wv = (const float*)d_in[7];
    const float* bv = (const float*)d_in[8];
    const float* Wp = (const float*)d_in[9];
    const float* bp = (const float*)d_in[10];
    float* out = (float*)d_out;

    dim3 gridP(EMB / 64, NROWS / 64);   // (4, 64)
    proj_kernel<0, 1><<<gridP, 256>>>(query, Wq, bq, nullptr);
    proj_kernel<0, 2><<<gridP, 256>>>(key_,  Wk, bk, nullptr);
    proj_kernel<0, 3><<<gridP, 256>>>(value, Wv, bv, nullptr);

    dim3 gridA(L_SEQ / 64, BATCH * NH); // (32, 16)
    attn_kernel<<<gridA, 128>>>();

    proj_kernel<1, 0><<<gridP, 256>>>(nullptr, Wp, bp, out);
}

// round 3
// speedup vs baseline: 2.1991x; 2.1991x over previous
#include <cuda_runtime.h>
#include <cstdint>

#define L_SEQ 2048
#define BATCH 2
#define EMB   256
#define NH    8
#define HD    32
#define NROWS (L_SEQ*BATCH)   // 4096
#define SCALE 0.17677669529663687f  // 32^-0.5

// Scratch (allocation-free).
// g_Q: [b][h][l][d], g_K: [b][h][d][l] (pre-transposed!), g_V: [b][h][l][d]
// g_AO: [l][b][e]
__device__ float g_Q[BATCH*NH*L_SEQ*HD];
__device__ float g_K[BATCH*NH*L_SEQ*HD];
__device__ float g_V[BATCH*NH*L_SEQ*HD];
__device__ float g_AO[NROWS*EMB];

// ---------------------------------------------------------------------------
// helpers: tf32 convert + m16n8k8 tf32 mma
// ---------------------------------------------------------------------------
__device__ __forceinline__ float f2tf(float f) {
    uint32_t u;
    asm("cvt.rna.tf32.f32 %0, %1;" : "=r"(u) : "f"(f));
    return __uint_as_float(u);
}

__device__ __forceinline__ void mma_tf32(float c[4],
    uint32_t a0, uint32_t a1, uint32_t a2, uint32_t a3,
    uint32_t b0, uint32_t b1)
{
    asm volatile(
        "mma.sync.aligned.m16n8k8.row.col.f32.tf32.tf32.f32 "
        "{%0,%1,%2,%3},{%4,%5,%6,%7},{%8,%9},{%0,%1,%2,%3};"
        : "+f"(c[0]), "+f"(c[1]), "+f"(c[2]), "+f"(c[3])
        : "r"(a0), "r"(a1), "r"(a2), "r"(a3), "r"(b0), "r"(b1));
}

// ---------------------------------------------------------------------------
// Projection GEMM (tf32 mma): C[4096,256] = X @ W + bias
// SRC_AO: 0 = X param, 1 = g_AO.  DST: 0 = Cout, 1 = g_Q, 2 = g_K(T), 3 = g_V
// CTA: 128 thr (4 warps), tile 64x64, k-step 32. Warp w owns rows m0=w*16.
// ---------------------------------------------------------------------------
template<int SRC_AO, int DST>
__global__ __launch_bounds__(128) void proj_kernel(
    const float* __restrict__ Xin, const float* __restrict__ W,
    const float* __restrict__ bias, float* __restrict__ Cout)
{
    __shared__ float Xs[64][36];   // stride 36: A-frag reads conflict-free
    __shared__ float Ws[32][68];   // stride 68: B-frag reads <=2-way

    const float* __restrict__ X = SRC_AO ? (const float*)g_AO : Xin;

    int tid  = threadIdx.x;
    int lane = tid & 31, warp = tid >> 5;
    int gid  = lane >> 2, tig = lane & 3;
    int m0   = warp * 16;
    int rowBase = blockIdx.y * 64;
    int colBase = blockIdx.x * 64;

    float cc[8][4];
    #pragma unroll
    for (int nn = 0; nn < 8; nn++)
        #pragma unroll
        for (int j = 0; j < 4; j++) cc[nn][j] = 0.f;

    for (int k0 = 0; k0 < EMB; k0 += 32) {
        __syncthreads();
        #pragma unroll
        for (int i = tid; i < 64 * 32; i += 128) {
            int r = i >> 5, kk = i & 31;
            Xs[r][kk] = f2tf(X[(rowBase + r) * EMB + k0 + kk]);
        }
        #pragma unroll
        for (int i = tid; i < 32 * 64; i += 128) {
            int kk = i >> 6, c = i & 63;
            Ws[kk][c] = f2tf(W[(k0 + kk) * EMB + colBase + c]);
        }
        __syncthreads();

        uint32_t a[4][4];
        #pragma unroll
        for (int kc = 0; kc < 4; kc++) {
            a[kc][0] = __float_as_uint(Xs[m0 + gid    ][kc * 8 + tig    ]);
            a[kc][1] = __float_as_uint(Xs[m0 + gid + 8][kc * 8 + tig    ]);
            a[kc][2] = __float_as_uint(Xs[m0 + gid    ][kc * 8 + tig + 4]);
            a[kc][3] = __float_as_uint(Xs[m0 + gid + 8][kc * 8 + tig + 4]);
        }
        #pragma unroll
        for (int nn = 0; nn < 8; nn++) {
            #pragma unroll
            for (int kc = 0; kc < 4; kc++) {
                uint32_t b0 = __float_as_uint(Ws[kc * 8 + tig    ][nn * 8 + gid]);
                uint32_t b1 = __float_as_uint(Ws[kc * 8 + tig + 4][nn * 8 + gid]);
                mma_tf32(cc[nn], a[kc][0], a[kc][1], a[kc][2], a[kc][3], b0, b1);
            }
        }
    }

    // epilogue: + bias, scatter per DST
    int r_lo = rowBase + m0 + gid;
    int r_hi = r_lo + 8;
    #pragma unroll
    for (int nn = 0; nn < 8; nn++) {
        int c0 = colBase + nn * 8 + 2 * tig;
        float b0 = bias[c0], b1 = bias[c0 + 1];
        float v00 = cc[nn][0] + b0, v01 = cc[nn][1] + b1;   // row r_lo
        float v10 = cc[nn][2] + b0, v11 = cc[nn][3] + b1;   // row r_hi
        if (DST == 0) {
            *(float2*)&Cout[r_lo * EMB + c0] = make_float2(v00, v01);
            *(float2*)&Cout[r_hi * EMB + c0] = make_float2(v10, v11);
        } else {
            int h = c0 >> 5, d = c0 & 31;   // c0 even, pair stays in same head
            if (DST == 2) {
                // K transposed: [b,h,d,l]
                int l0 = r_lo >> 1, bb0 = r_lo & 1;
                int l1 = r_hi >> 1, bb1 = r_hi & 1;
                float* base0 = g_K + ((size_t)(bb0 * NH + h) * HD) * L_SEQ;
                float* base1 = g_K + ((size_t)(bb1 * NH + h) * HD) * L_SEQ;
                base0[(size_t)d * L_SEQ + l0]       = v00;
                base0[(size_t)(d + 1) * L_SEQ + l0] = v01;
                base1[(size_t)d * L_SEQ + l1]       = v10;
                base1[(size_t)(d + 1) * L_SEQ + l1] = v11;
            } else {
                float* dst = (DST == 1) ? g_Q : g_V;
                int l0 = r_lo >> 1, bb0 = r_lo & 1;
                int l1 = r_hi >> 1, bb1 = r_hi & 1;
                *(float2*)&dst[(((size_t)(bb0 * NH + h) * L_SEQ) + l0) * HD + d] =
                    make_float2(v00, v01);
                *(float2*)&dst[(((size_t)(bb1 * NH + h) * L_SEQ) + l1) * HD + d] =
                    make_float2(v10, v11);
            }
        }
    }
}

// ---------------------------------------------------------------------------
// Flash attention, tf32 mma. CTA = (b,h) x 64-query tile, 4 warps x 16 rows.
// S and O live in mma fragments; P relayouts through smem.
// ---------------------------------------------------------------------------
__global__ __launch_bounds__(128) void attn_kernel()
{
    __shared__ float Qs[64][36];
    __shared__ float Ks[32][68];   // [d][k_col]
    __shared__ float Vs[64][36];   // [k][d]
    __shared__ float Ps[64][68];   // probs (tf32)

    int bh = blockIdx.y;
    int q0 = blockIdx.x * 64;
    const float* __restrict__ Qp = g_Q + (size_t)bh * (L_SEQ * HD);
    const float* __restrict__ Kp = g_K + (size_t)bh * (HD * L_SEQ);
    const float* __restrict__ Vp = g_V + (size_t)bh * (L_SEQ * HD);

    int tid  = threadIdx.x;
    int lane = tid & 31, warp = tid >> 5;
    int gid  = lane >> 2, tig = lane & 3;
    int m0   = warp * 16;

    // load Q (scaled, tf32)
    #pragma unroll
    for (int i = tid; i < 64 * 32; i += 128) {
        int r = i >> 5, d = i & 31;
        Qs[r][d] = f2tf(Qp[(q0 + r) * HD + d] * SCALE);
    }
    __syncthreads();

    // preload Q A-fragments (reused for every key tile)
    uint32_t aq[4][4];
    #pragma unroll
    for (int kc = 0; kc < 4; kc++) {
        aq[kc][0] = __float_as_uint(Qs[m0 + gid    ][kc * 8 + tig    ]);
        aq[kc][1] = __float_as_uint(Qs[m0 + gid + 8][kc * 8 + tig    ]);
        aq[kc][2] = __float_as_uint(Qs[m0 + gid    ][kc * 8 + tig + 4]);
        aq[kc][3] = __float_as_uint(Qs[m0 + gid + 8][kc * 8 + tig + 4]);
    }

    float m_lo = -1e30f, m_hi = -1e30f, l_lo = 0.f, l_hi = 0.f;
    float oc[4][4];
    #pragma unroll
    for (int nf = 0; nf < 4; nf++)
        #pragma unroll
        for (int j = 0; j < 4; j++) oc[nf][j] = 0.f;

    for (int kt = 0; kt < L_SEQ; kt += 64) {
        __syncthreads();   // prior PV done before overwriting Ks/Vs
        #pragma unroll
        for (int i = tid; i < 32 * 64; i += 128) {
            int d = i >> 6, r = i & 63;
            Ks[d][r] = f2tf(Kp[(size_t)d * L_SEQ + kt + r]);
        }
        #pragma unroll
        for (int i = tid; i < 64 * 32; i += 128) {
            int r = i >> 5, d = i & 31;
            Vs[r][d] = f2tf(Vp[(kt + r) * HD + d]);
        }
        __syncthreads();

        // ---- S = Q K^T ----
        float sc[8][4];
        #pragma unroll
        for (int nn = 0; nn < 8; nn++)
            #pragma unroll
            for (int j = 0; j < 4; j++) sc[nn][j] = 0.f;
        #pragma unroll
        for (int nn = 0; nn < 8; nn++) {
            #pragma unroll
            for (int kc = 0; kc < 4; kc++) {
                uint32_t b0 = __float_as_uint(Ks[kc * 8 + tig    ][nn * 8 + gid]);
                uint32_t b1 = __float_as_uint(Ks[kc * 8 + tig + 4][nn * 8 + gid]);
                mma_tf32(sc[nn], aq[kc][0], aq[kc][1], aq[kc][2], aq[kc][3], b0, b1);
            }
        }

        // ---- online softmax on fragments ----
        float mx_lo = -1e30f, mx_hi = -1e30f;
        #pragma unroll
        for (int nn = 0; nn < 8; nn++) {
            mx_lo = fmaxf(mx_lo, fmaxf(sc[nn][0], sc[nn][1]));
            mx_hi = fmaxf(mx_hi, fmaxf(sc[nn][2], sc[nn][3]));
        }
        mx_lo = fmaxf(mx_lo, __shfl_xor_sync(0xffffffffu, mx_lo, 1));
        mx_lo = fmaxf(mx_lo, __shfl_xor_sync(0xffffffffu, mx_lo, 2));
        mx_hi = fmaxf(mx_hi, __shfl_xor_sync(0xffffffffu, mx_hi, 1));
        mx_hi = fmaxf(mx_hi, __shfl_xor_sync(0xffffffffu, mx_hi, 2));

        float mn_lo = fmaxf(m_lo, mx_lo), mn_hi = fmaxf(m_hi, mx_hi);
        float al_lo = __expf(m_lo - mn_lo), al_hi = __expf(m_hi - mn_hi);
        m_lo = mn_lo; m_hi = mn_hi;

        float sum_lo = 0.f, sum_hi = 0.f;
        #pragma unroll
        for (int nn = 0; nn < 8; nn++) {
            float p0 = __expf(sc[nn][0] - mn_lo);
            float p1 = __expf(sc[nn][1] - mn_lo);
            float p2 = __expf(sc[nn][2] - mn_hi);
            float p3 = __expf(sc[nn][3] - mn_hi);
            sum_lo += p0 + p1;
            sum_hi += p2 + p3;
            int cc = nn * 8 + 2 * tig;
            *(float2*)&Ps[m0 + gid    ][cc] = make_float2(f2tf(p0), f2tf(p1));
            *(float2*)&Ps[m0 + gid + 8][cc] = make_float2(f2tf(p2), f2tf(p3));
        }
        sum_lo += __shfl_xor_sync(0xffffffffu, sum_lo, 1);
        sum_lo += __shfl_xor_sync(0xffffffffu, sum_lo, 2);
        sum_hi += __shfl_xor_sync(0xffffffffu, sum_hi, 1);
        sum_hi += __shfl_xor_sync(0xffffffffu, sum_hi, 2);
        l_lo = l_lo * al_lo + sum_lo;
        l_hi = l_hi * al_hi + sum_hi;

        #pragma unroll
        for (int nf = 0; nf < 4; nf++) {
            oc[nf][0] *= al_lo; oc[nf][1] *= al_lo;
            oc[nf][2] *= al_hi; oc[nf][3] *= al_hi;
        }
        __syncwarp();   // Ps rows of this warp visible warp-wide

        // ---- O += P V ----
        #pragma unroll
        for (int kc = 0; kc < 8; kc++) {
            uint32_t pa0 = __float_as_uint(Ps[m0 + gid    ][kc * 8 + tig    ]);
            uint32_t pa1 = __float_as_uint(Ps[m0 + gid + 8][kc * 8 + tig    ]);
            uint32_t pa2 = __float_as_uint(Ps[m0 + gid    ][kc * 8 + tig + 4]);
            uint32_t pa3 = __float_as_uint(Ps[m0 + gid + 8][kc * 8 + tig + 4]);
            #pragma unroll
            for (int nf = 0; nf < 4; nf++) {
                uint32_t b0 = __float_as_uint(Vs[kc * 8 + tig    ][nf * 8 + gid]);
                uint32_t b1 = __float_as_uint(Vs[kc * 8 + tig + 4][nf * 8 + gid]);
                mma_tf32(oc[nf], pa0, pa1, pa2, pa3, b0, b1);
            }
        }
    }

    // ---- normalize + store to g_AO [l][b][e] ----
    float inv_lo = 1.f / l_lo, inv_hi = 1.f / l_hi;
    int b = bh >> 3, h = bh & 7;
    int l_row_lo = q0 + m0 + gid;
    int l_row_hi = l_row_lo + 8;
    #pragma unroll
    for (int nf = 0; nf < 4; nf++) {
        int col = h * HD + nf * 8 + 2 * tig;
        *(float2*)&g_AO[((size_t)l_row_lo * BATCH + b) * EMB + col] =
            make_float2(oc[nf][0] * inv_lo, oc[nf][1] * inv_lo);
        *(float2*)&g_AO[((size_t)l_row_hi * BATCH + b) * EMB + col] =
            make_float2(oc[nf][2] * inv_hi, oc[nf][3] * inv_hi);
    }
}

// ---------------------------------------------------------------------------
extern "C" void kernel_launch(void* const* d_in, const int* in_sizes, int n_in,
                              void* d_out, int out_size)
{
    const float* query = (const float*)d_in[0];
    const float* key_  = (const float*)d_in[1];
    const float* value = (const float*)d_in[2];
    const float* Wq = (const float*)d_in[3];
    const float* bq = (const float*)d_in[4];
    const float* Wk = (const float*)d_in[5];
    const float* bk = (const float*)d_in[6];
    const float* Wv = (const float*)d_in[7];
    const float* bv = (const float*)d_in[8];
    const float* Wp = (const float*)d_in[9];
    const float* bp = (const float*)d_in[10];
    float* out = (float*)d_out;

    dim3 gridP(EMB / 64, NROWS / 64);   // (4, 64)
    proj_kernel<0, 1><<<gridP, 128>>>(query, Wq, bq, nullptr);
    proj_kernel<0, 2><<<gridP, 128>>>(key_,  Wk, bk, nullptr);
    proj_kernel<0, 3><<<gridP, 128>>>(value, Wv, bv, nullptr);

    dim3 gridA(L_SEQ / 64, BATCH * NH); // (32, 16)
    attn_kernel<<<gridA, 128>>>();

    proj_kernel<1, 0><<<gridP, 128>>>(nullptr, Wp, bp, out);
}

// round 4
// speedup vs baseline: 4.0432x; 1.8386x over previous
#include <cuda_runtime.h>
#include <cuda_fp16.h>
#include <cstdint>

#define L_SEQ 2048
#define BATCH 2
#define EMB   256
#define NH    8
#define HD    32
#define NROWS (L_SEQ*BATCH)   // 4096
#define SCALE 0.17677669529663687f  // 32^-0.5

// Scratch (allocation-free), all fp16:
// g_Q: [b][h][l][d/2]  half2 pairs along d  (A-frag friendly, pre-scaled by SCALE)
// g_K: [b][h][d/2][l]  half2 pairs along d  (B-frag friendly for S=QK^T)
// g_V: [b][h][l/2][d][2] halves, pairs along l (B-frag friendly for PV)
// g_AO:[l][b][e/2]     half2 pairs along e  (A-frag friendly for final proj)
__device__ __half2 g_Q[BATCH*NH*L_SEQ*(HD/2)];
__device__ __half2 g_K[BATCH*NH*(HD/2)*L_SEQ];
__device__ __half  g_V[BATCH*NH*L_SEQ*HD];
__device__ __half2 g_AO[NROWS*(EMB/2)];

// ---------------------------------------------------------------------------
__device__ __forceinline__ uint32_t h2u(__half2 h) {
    return *reinterpret_cast<uint32_t*>(&h);
}
__device__ __forceinline__ uint32_t pack2(float x, float y) {
    __half2 h = __floats2half2_rn(x, y);
    return *reinterpret_cast<uint32_t*>(&h);
}

// m16n8k16 f16 mma, fp32 accumulate
__device__ __forceinline__ void mma_f16(float c[4],
    uint32_t a0, uint32_t a1, uint32_t a2, uint32_t a3,
    uint32_t b0, uint32_t b1)
{
    asm volatile(
        "mma.sync.aligned.m16n8k16.row.col.f32.f16.f16.f32 "
        "{%0,%1,%2,%3},{%4,%5,%6,%7},{%8,%9},{%0,%1,%2,%3};"
        : "+f"(c[0]), "+f"(c[1]), "+f"(c[2]), "+f"(c[3])
        : "r"(a0), "r"(a1), "r"(a2), "r"(a3), "r"(b0), "r"(b1));
}

// ---------------------------------------------------------------------------
// Projection GEMM (f16 mma): C[4096,256] = X @ W + bias
// SRC_AO: 0 = X param (fp32), 1 = g_AO (fp16).
// DST: 0 = Cout fp32, 1 = g_Q (scaled), 2 = g_K (d-major), 3 = g_V (l-paired)
// CTA: 128 thr (4 warps), tile 64x64, k-step 32.
// ---------------------------------------------------------------------------
template<int SRC_AO, int DST>
__global__ __launch_bounds__(128) void proj_kernel(
    const float* __restrict__ Xin, const float* __restrict__ W,
    const float* __restrict__ bias, float* __restrict__ Cout)
{
    __shared__ __half2 Xs[64][20];   // [row][k2], stride 20 (=4 mod 32 banks): A-frag conflict-free
    __shared__ __half2 Ws[16][72];   // [k2][n],  stride 72 (=8 mod 32 banks): B-frag conflict-free

    int tid  = threadIdx.x;
    int lane = tid & 31, warp = tid >> 5;
    int gid  = lane >> 2, tig = lane & 3;
    int m0   = warp * 16;
    int rowBase = blockIdx.y * 64;
    int colBase = blockIdx.x * 64;

    float cc[8][4];
    #pragma unroll
    for (int nn = 0; nn < 8; nn++)
        #pragma unroll
        for (int j = 0; j < 4; j++) cc[nn][j] = 0.f;

    for (int k0 = 0; k0 < EMB; k0 += 32) {
        __syncthreads();
        #pragma unroll
        for (int i = tid; i < 64 * 16; i += 128) {
            int r = i >> 4, k2 = i & 15;
            if (SRC_AO) {
                Xs[r][k2] = g_AO[(size_t)(rowBase + r) * (EMB/2) + (k0 >> 1) + k2];
            } else {
                float2 x = *(const float2*)&Xin[(size_t)(rowBase + r) * EMB + k0 + 2 * k2];
                Xs[r][k2] = __floats2half2_rn(x.x, x.y);
            }
        }
        #pragma unroll
        for (int i = tid; i < 16 * 64; i += 128) {
            int k2 = i >> 6, c = i & 63;
            Ws[k2][c] = __floats2half2_rn(
                W[(size_t)(k0 + 2 * k2)     * EMB + colBase + c],
                W[(size_t)(k0 + 2 * k2 + 1) * EMB + colBase + c]);
        }
        __syncthreads();

        uint32_t a[2][4];
        #pragma unroll
        for (int kc = 0; kc < 2; kc++) {
            a[kc][0] = h2u(Xs[m0 + gid    ][kc * 8 + tig    ]);
            a[kc][1] = h2u(Xs[m0 + gid + 8][kc * 8 + tig    ]);
            a[kc][2] = h2u(Xs[m0 + gid    ][kc * 8 + tig + 4]);
            a[kc][3] = h2u(Xs[m0 + gid + 8][kc * 8 + tig + 4]);
        }
        #pragma unroll
        for (int nn = 0; nn < 8; nn++) {
            #pragma unroll
            for (int kc = 0; kc < 2; kc++) {
                uint32_t b0 = h2u(Ws[kc * 8 + tig    ][nn * 8 + gid]);
                uint32_t b1 = h2u(Ws[kc * 8 + tig + 4][nn * 8 + gid]);
                mma_f16(cc[nn], a[kc][0], a[kc][1], a[kc][2], a[kc][3], b0, b1);
            }
        }
    }

    // epilogue
    int r_lo = rowBase + m0 + gid;
    int r_hi = r_lo + 8;
    #pragma unroll
    for (int nn = 0; nn < 8; nn++) {
        int c0 = colBase + nn * 8 + 2 * tig;
        float bv0 = bias[c0], bv1 = bias[c0 + 1];
        float v00 = cc[nn][0] + bv0, v01 = cc[nn][1] + bv1;   // row r_lo
        float v10 = cc[nn][2] + bv0, v11 = cc[nn][3] + bv1;   // row r_hi
        if (DST == 0) {
            *(float2*)&Cout[(size_t)r_lo * EMB + c0] = make_float2(v00, v01);
            *(float2*)&Cout[(size_t)r_hi * EMB + c0] = make_float2(v10, v11);
        } else {
            int h = (c0 >> 5) & 7, d = c0 & 31;   // c0 even -> pair stays in head
            int l0 = r_lo >> 1, b0i = r_lo & 1;   // row = l*B + b
            int l1 = r_hi >> 1, b1i = r_hi & 1;
            int bh0 = b0i * NH + h, bh1 = b1i * NH + h;
            if (DST == 1) {
                g_Q[((size_t)bh0 * L_SEQ + l0) * (HD/2) + (d >> 1)] =
                    __floats2half2_rn(v00 * SCALE, v01 * SCALE);
                g_Q[((size_t)bh1 * L_SEQ + l1) * (HD/2) + (d >> 1)] =
                    __floats2half2_rn(v10 * SCALE, v11 * SCALE);
            } else if (DST == 2) {
                g_K[((size_t)bh0 * (HD/2) + (d >> 1)) * L_SEQ + l0] = __floats2half2_rn(v00, v01);
                g_K[((size_t)bh1 * (HD/2) + (d >> 1)) * L_SEQ + l1] = __floats2half2_rn(v10, v11);
            } else {
                // V: halves at ((bh*(L/2)+l2)*HD + d)*2 + (l&1)
                g_V[(((size_t)bh0 * (L_SEQ/2) + (l0 >> 1)) * HD + d    ) * 2 + (l0 & 1)] = __float2half_rn(v00);
                g_V[(((size_t)bh0 * (L_SEQ/2) + (l0 >> 1)) * HD + d + 1) * 2 + (l0 & 1)] = __float2half_rn(v01);
                g_V[(((size_t)bh1 * (L_SEQ/2) + (l1 >> 1)) * HD + d    ) * 2 + (l1 & 1)] = __float2half_rn(v10);
                g_V[(((size_t)bh1 * (L_SEQ/2) + (l1 >> 1)) * HD + d + 1) * 2 + (l1 & 1)] = __float2half_rn(v11);
            }
        }
    }
}

// ---------------------------------------------------------------------------
// Flash attention, f16 mma. CTA = (b,h) x 64-query tile, 4 warps x 16 rows.
// P converts C-frag -> A-frag in registers (no smem round-trip).
// ---------------------------------------------------------------------------
__global__ __launch_bounds__(128) void attn_kernel()
{
    __shared__ __half2 Ks[16][72];   // [d2][key],  stride 72 (=8 mod 32): conflict-free
    __shared__ __half2 Vs[32][40];   // [k2][d],    stride 40 (=8 mod 32): conflict-free

    int bh = blockIdx.y;
    int q0 = blockIdx.x * 64;
    int tid  = threadIdx.x;
    int lane = tid & 31, warp = tid >> 5;
    int gid  = lane >> 2, tig = lane & 3;
    int m0   = warp * 16;

    const __half2* __restrict__ Qh = g_Q + (size_t)bh * L_SEQ * (HD/2);
    const __half2* __restrict__ Kh = g_K + (size_t)bh * (HD/2) * L_SEQ;
    const __half2* __restrict__ Vh =
        reinterpret_cast<const __half2*>(g_V) + (size_t)bh * (L_SEQ/2) * HD;

    // Q A-fragments straight from gmem (reused all key tiles)
    uint32_t aq[2][4];
    #pragma unroll
    for (int kc = 0; kc < 2; kc++) {
        aq[kc][0] = h2u(Qh[(size_t)(q0 + m0 + gid    ) * (HD/2) + kc * 8 + tig    ]);
        aq[kc][1] = h2u(Qh[(size_t)(q0 + m0 + gid + 8) * (HD/2) + kc * 8 + tig    ]);
        aq[kc][2] = h2u(Qh[(size_t)(q0 + m0 + gid    ) * (HD/2) + kc * 8 + tig + 4]);
        aq[kc][3] = h2u(Qh[(size_t)(q0 + m0 + gid + 8) * (HD/2) + kc * 8 + tig + 4]);
    }

    float m_lo = -1e30f, m_hi = -1e30f, l_lo = 0.f, l_hi = 0.f;
    float oc[4][4];
    #pragma unroll
    for (int nf = 0; nf < 4; nf++)
        #pragma unroll
        for (int j = 0; j < 4; j++) oc[nf][j] = 0.f;

    for (int kt = 0; kt < L_SEQ; kt += 64) {
        __syncthreads();
        #pragma unroll
        for (int i = tid; i < 16 * 64; i += 128) {
            int d2 = i >> 6, key = i & 63;
            Ks[d2][key] = Kh[(size_t)d2 * L_SEQ + kt + key];
        }
        #pragma unroll
        for (int i = tid; i < 32 * 32; i += 128) {
            int k2 = i >> 5, d = i & 31;
            Vs[k2][d] = Vh[(size_t)((kt >> 1) + k2) * HD + d];
        }
        __syncthreads();

        // ---- S = Q K^T ----
        float sc[8][4];
        #pragma unroll
        for (int nn = 0; nn < 8; nn++)
            #pragma unroll
            for (int j = 0; j < 4; j++) sc[nn][j] = 0.f;
        #pragma unroll
        for (int nn = 0; nn < 8; nn++) {
            #pragma unroll
            for (int kc = 0; kc < 2; kc++) {
                uint32_t b0 = h2u(Ks[kc * 8 + tig    ][nn * 8 + gid]);
                uint32_t b1 = h2u(Ks[kc * 8 + tig + 4][nn * 8 + gid]);
                mma_f16(sc[nn], aq[kc][0], aq[kc][1], aq[kc][2], aq[kc][3], b0, b1);
            }
        }

        // ---- online softmax on fragments (p written back into sc) ----
        float mx_lo = -1e30f, mx_hi = -1e30f;
        #pragma unroll
        for (int nn = 0; nn < 8; nn++) {
            mx_lo = fmaxf(mx_lo, fmaxf(sc[nn][0], sc[nn][1]));
            mx_hi = fmaxf(mx_hi, fmaxf(sc[nn][2], sc[nn][3]));
        }
        mx_lo = fmaxf(mx_lo, __shfl_xor_sync(0xffffffffu, mx_lo, 1));
        mx_lo = fmaxf(mx_lo, __shfl_xor_sync(0xffffffffu, mx_lo, 2));
        mx_hi = fmaxf(mx_hi, __shfl_xor_sync(0xffffffffu, mx_hi, 1));
        mx_hi = fmaxf(mx_hi, __shfl_xor_sync(0xffffffffu, mx_hi, 2));

        float mn_lo = fmaxf(m_lo, mx_lo), mn_hi = fmaxf(m_hi, mx_hi);
        float al_lo = __expf(m_lo - mn_lo), al_hi = __expf(m_hi - mn_hi);
        m_lo = mn_lo; m_hi = mn_hi;

        float sum_lo = 0.f, sum_hi = 0.f;
        #pragma unroll
        for (int nn = 0; nn < 8; nn++) {
            float p0 = __expf(sc[nn][0] - mn_lo);
            float p1 = __expf(sc[nn][1] - mn_lo);
            float p2 = __expf(sc[nn][2] - mn_hi);
            float p3 = __expf(sc[nn][3] - mn_hi);
            sum_lo += p0 + p1;  sum_hi += p2 + p3;
            sc[nn][0] = p0; sc[nn][1] = p1; sc[nn][2] = p2; sc[nn][3] = p3;
        }
        sum_lo += __shfl_xor_sync(0xffffffffu, sum_lo, 1);
        sum_lo += __shfl_xor_sync(0xffffffffu, sum_lo, 2);
        sum_hi += __shfl_xor_sync(0xffffffffu, sum_hi, 1);
        sum_hi += __shfl_xor_sync(0xffffffffu, sum_hi, 2);
        l_lo = l_lo * al_lo + sum_lo;
        l_hi = l_hi * al_hi + sum_hi;

        #pragma unroll
        for (int nf = 0; nf < 4; nf++) {
            oc[nf][0] *= al_lo; oc[nf][1] *= al_lo;
            oc[nf][2] *= al_hi; oc[nf][3] *= al_hi;
        }

        // ---- O += P V  (P C-frags pack directly into A-frags, in registers) ----
        #pragma unroll
        for (int kc = 0; kc < 4; kc++) {
            uint32_t a0 = pack2(sc[2*kc    ][0], sc[2*kc    ][1]);
            uint32_t a1 = pack2(sc[2*kc    ][2], sc[2*kc    ][3]);
            uint32_t a2 = pack2(sc[2*kc + 1][0], sc[2*kc + 1][1]);
            uint32_t a3 = pack2(sc[2*kc + 1][2], sc[2*kc + 1][3]);
            #pragma unroll
            for (int nf = 0; nf < 4; nf++) {
                uint32_t b0 = h2u(Vs[kc * 8 + tig    ][nf * 8 + gid]);
                uint32_t b1 = h2u(Vs[kc * 8 + tig + 4][nf * 8 + gid]);
                mma_f16(oc[nf], a0, a1, a2, a3, b0, b1);
            }
        }
    }

    // ---- normalize + store to g_AO [l][b][e/2] (fp16) ----
    float inv_lo = 1.f / l_lo, inv_hi = 1.f / l_hi;
    int b = bh >> 3, h = bh & 7;
    int r_lo = q0 + m0 + gid, r_hi = r_lo + 8;
    #pragma unroll
    for (int nf = 0; nf < 4; nf++) {
        int c2 = h * 16 + nf * 4 + tig;   // half2 column index within E/2
        g_AO[((size_t)r_lo * BATCH + b) * (EMB/2) + c2] =
            __floats2half2_rn(oc[nf][0] * inv_lo, oc[nf][1] * inv_lo);
        g_AO[((size_t)r_hi * BATCH + b) * (EMB/2) + c2] =
            __floats2half2_rn(oc[nf][2] * inv_hi, oc[nf][3] * inv_hi);
    }
}

// ---------------------------------------------------------------------------
extern "C" void kernel_launch(void* const* d_in, const int* in_sizes, int n_in,
                              void* d_out, int out_size)
{
    const float* query = (const float*)d_in[0];
    const float* key_  = (const float*)d_in[1];
    const float* value = (const float*)d_in[2];
    const float* Wq = (const float*)d_in[3];
    const float* bq = (const float*)d_in[4];
    const float* Wk = (const float*)d_in[5];
    const float* bk = (const float*)d_in[6];
    const float* Wv = (const float*)d_in[7];
    const float* bv = (const float*)d_in[8];
    const float* Wp = (const float*)d_in[9];
    const float* bp = (const float*)d_in[10];
    float* out = (float*)d_out;

    dim3 gridP(EMB / 64, NROWS / 64);   // (4, 64)
    proj_kernel<0, 1><<<gridP, 128>>>(query, Wq, bq, nullptr);
    proj_kernel<0, 2><<<gridP, 128>>>(key_,  Wk, bk, nullptr);
    proj_kernel<0, 3><<<gridP, 128>>>(value, Wv, bv, nullptr);

    dim3 gridA(L_SEQ / 64, BATCH * NH); // (32, 16)
    attn_kernel<<<gridA, 128>>>();

    proj_kernel<1, 0><<<gridP, 128>>>(nullptr, Wp, bp, out);
}

// round 5
// speedup vs baseline: 4.7984x; 1.1868x over previous
#include <cuda_runtime.h>
#include <cuda_fp16.h>
#include <cstdint>

#define L_SEQ 2048
#define BATCH 2
#define EMB   256
#define NH    8
#define HD    32
#define NROWS (L_SEQ*BATCH)   // 4096
#define KT    128             // attention key tile
// SCALE * log2(e): softmax done in exp2 domain
#define SCALE_LOG2E 0.25500927171408637f

// Scratch (allocation-free), fp16:
// g_Q : [b][h][l][d/2] half2  (pre-scaled by SCALE*log2e)
// g_K : [b][h][d][l]   half   (row-major d-major for ldmatrix.trans)
// g_V : [b][h][l][d/2] half2
// g_AO: [l][b][e/2]    half2
__device__ __half2 g_Q[BATCH*NH*L_SEQ*(HD/2)];
__device__ __half  g_K[BATCH*NH*HD*L_SEQ];
__device__ __half2 g_V[BATCH*NH*L_SEQ*(HD/2)];
__device__ __half2 g_AO[NROWS*(EMB/2)];

// ---------------------------------------------------------------------------
__device__ __forceinline__ uint32_t pack2(float x, float y) {
    __half2 h = __floats2half2_rn(x, y);
    return *reinterpret_cast<uint32_t*>(&h);
}
__device__ __forceinline__ float ex2(float x) {
    float y; asm("ex2.approx.ftz.f32 %0, %1;" : "=f"(y) : "f"(x)); return y;
}
__device__ __forceinline__ void mma_f16(float c[4],
    uint32_t a0, uint32_t a1, uint32_t a2, uint32_t a3,
    uint32_t b0, uint32_t b1)
{
    asm volatile(
        "mma.sync.aligned.m16n8k16.row.col.f32.f16.f16.f32 "
        "{%0,%1,%2,%3},{%4,%5,%6,%7},{%8,%9},{%0,%1,%2,%3};"
        : "+f"(c[0]), "+f"(c[1]), "+f"(c[2]), "+f"(c[3])
        : "r"(a0), "r"(a1), "r"(a2), "r"(a3), "r"(b0), "r"(b1));
}
// ldmatrix x4, no transpose (A-fragments)
__device__ __forceinline__ void ldsm4(uint32_t r[4], uint32_t addr) {
    asm volatile("ldmatrix.sync.aligned.m8n8.x4.shared.b16 {%0,%1,%2,%3},[%4];"
        : "=r"(r[0]), "=r"(r[1]), "=r"(r[2]), "=r"(r[3]) : "r"(addr));
}
// ldmatrix x4 transposed (B-fragments from [k][n] row-major)
__device__ __forceinline__ void ldsm4t(uint32_t r[4], uint32_t addr) {
    asm volatile("ldmatrix.sync.aligned.m8n8.x4.trans.shared.b16 {%0,%1,%2,%3},[%4];"
        : "=r"(r[0]), "=r"(r[1]), "=r"(r[2]), "=r"(r[3]) : "r"(addr));
}

// ---------------------------------------------------------------------------
// Projection GEMM: C[4096,256] = X @ W + bias (f16 mma + ldmatrix)
// SRC_AO: 0 = X fp32 param, 1 = g_AO (fp16).
// dst: 0 = Cout fp32, 1 = g_Q (scaled), 2 = g_K ([d][l]), 3 = g_V
// CTA: 128 thr (4 warps), tile 64x64, k-step 32.
// ---------------------------------------------------------------------------
template<int SRC_AO>
__global__ __launch_bounds__(128) void proj_kernel(
    const float* __restrict__ X0, const float* __restrict__ X1, const float* __restrict__ X2,
    const float* __restrict__ W0, const float* __restrict__ W1, const float* __restrict__ W2,
    const float* __restrict__ B0, const float* __restrict__ B1, const float* __restrict__ B2,
    float* __restrict__ Cout)
{
    __shared__ __align__(16) __half Xs[64][40];   // rows 80B: ldmatrix conflict-free (20r)
    __shared__ __align__(16) __half Ws[32][72];   // rows 144B: ldmatrix conflict-free (4r)

    int z = blockIdx.z;
    const float* __restrict__ X    = (z == 0) ? X0 : (z == 1) ? X1 : X2;
    const float* __restrict__ W    = (z == 0) ? W0 : (z == 1) ? W1 : W2;
    const float* __restrict__ bias = (z == 0) ? B0 : (z == 1) ? B1 : B2;
    int dst = SRC_AO ? 0 : (z + 1);

    int tid  = threadIdx.x;
    int lane = tid & 31, warp = tid >> 5;
    int gid  = lane >> 2, tig = lane & 3;
    int m0   = warp * 16;
    int rowBase = blockIdx.y * 64;
    int colBase = blockIdx.x * 64;

    uint32_t xs_base = (uint32_t)__cvta_generic_to_shared(&Xs[0][0]);
    uint32_t ws_base = (uint32_t)__cvta_generic_to_shared(&Ws[0][0]);

    float cc[8][4];
    #pragma unroll
    for (int nn = 0; nn < 8; nn++)
        #pragma unroll
        for (int j = 0; j < 4; j++) cc[nn][j] = 0.f;

    for (int k0 = 0; k0 < EMB; k0 += 32) {
        __syncthreads();
        if (SRC_AO) {
            // g_AO rows: 128 half2; copy k-slice of 16 half2 = 4 uint4 per row
            #pragma unroll
            for (int i = tid; i < 64 * 4; i += 128) {
                int r = i >> 2, c = i & 3;
                *(uint4*)&Xs[r][c * 8] =
                    *((const uint4*)(g_AO + (size_t)(rowBase + r) * (EMB/2) + (k0 >> 1)) + c);
            }
        } else {
            #pragma unroll
            for (int i = tid; i < 64 * 16; i += 128) {
                int r = i >> 4, k2 = i & 15;
                float2 x = *(const float2*)&X[(size_t)(rowBase + r) * EMB + k0 + 2 * k2];
                *(__half2*)&Xs[r][2 * k2] = __floats2half2_rn(x.x, x.y);
            }
        }
        #pragma unroll
        for (int i = tid; i < 32 * 32; i += 128) {
            int k = i >> 5, c2 = i & 31;
            float2 w = *(const float2*)&W[(size_t)(k0 + k) * EMB + colBase + 2 * c2];
            *(__half2*)&Ws[k][2 * c2] = __floats2half2_rn(w.x, w.y);
        }
        __syncthreads();

        uint32_t a[2][4];
        #pragma unroll
        for (int kc = 0; kc < 2; kc++) {
            int m = lane >> 3;                      // matrix 0..3
            int row = m0 + (m & 1) * 8 + (lane & 7);
            int koff = kc * 16 + (m >> 1) * 8;
            ldsm4(a[kc], xs_base + row * 80 + koff * 2);
        }
        #pragma unroll
        for (int nn = 0; nn < 8; nn++) {
            uint32_t b[4];
            ldsm4t(b, ws_base + lane * 144 + nn * 16);
            mma_f16(cc[nn], a[0][0], a[0][1], a[0][2], a[0][3], b[0], b[1]);
            mma_f16(cc[nn], a[1][0], a[1][1], a[1][2], a[1][3], b[2], b[3]);
        }
    }

    // epilogue
    int r_lo = rowBase + m0 + gid;
    int r_hi = r_lo + 8;
    #pragma unroll
    for (int nn = 0; nn < 8; nn++) {
        int c0 = colBase + nn * 8 + 2 * tig;
        float bv0 = bias[c0], bv1 = bias[c0 + 1];
        float v00 = cc[nn][0] + bv0, v01 = cc[nn][1] + bv1;   // row r_lo
        float v10 = cc[nn][2] + bv0, v11 = cc[nn][3] + bv1;   // row r_hi
        if (dst == 0) {
            *(float2*)&Cout[(size_t)r_lo * EMB + c0] = make_float2(v00, v01);
            *(float2*)&Cout[(size_t)r_hi * EMB + c0] = make_float2(v10, v11);
        } else {
            int h = (c0 >> 5) & 7, d = c0 & 31;
            int l0 = r_lo >> 1, b0i = r_lo & 1;     // row = l*B + b
            int l1 = r_hi >> 1, b1i = r_hi & 1;
            int bh0 = b0i * NH + h, bh1 = b1i * NH + h;
            if (dst == 1) {
                g_Q[((size_t)bh0 * L_SEQ + l0) * (HD/2) + (d >> 1)] =
                    __floats2half2_rn(v00 * SCALE_LOG2E, v01 * SCALE_LOG2E);
                g_Q[((size_t)bh1 * L_SEQ + l1) * (HD/2) + (d >> 1)] =
                    __floats2half2_rn(v10 * SCALE_LOG2E, v11 * SCALE_LOG2E);
            } else if (dst == 2) {
                g_K[((size_t)bh0 * HD + d    ) * L_SEQ + l0] = __float2half_rn(v00);
                g_K[((size_t)bh0 * HD + d + 1) * L_SEQ + l0] = __float2half_rn(v01);
                g_K[((size_t)bh1 * HD + d    ) * L_SEQ + l1] = __float2half_rn(v10);
                g_K[((size_t)bh1 * HD + d + 1) * L_SEQ + l1] = __float2half_rn(v11);
            } else {
                g_V[((size_t)bh0 * L_SEQ + l0) * (HD/2) + (d >> 1)] = __floats2half2_rn(v00, v01);
                g_V[((size_t)bh1 * L_SEQ + l1) * (HD/2) + (d >> 1)] = __floats2half2_rn(v10, v11);
            }
        }
    }
}

// ---------------------------------------------------------------------------
// Flash attention: CTA = (b,h) x 64-query tile, 4 warps x 16 rows, 128-key tiles.
// B-fragments via ldmatrix.x4.trans; P stays in registers; softmax in exp2 domain.
// ---------------------------------------------------------------------------
__global__ __launch_bounds__(128) void attn_kernel()
{
    __shared__ __align__(16) __half Ks[32][136];   // [d][key], rows 272B
    __shared__ __align__(16) __half Vs[128][40];   // [key][d], rows 80B

    int bh = blockIdx.y;
    int q0 = blockIdx.x * 64;
    int tid  = threadIdx.x;
    int lane = tid & 31, warp = tid >> 5;
    int gid  = lane >> 2, tig = lane & 3;
    int m0   = warp * 16;

    const __half2* __restrict__ Qh = g_Q + (size_t)bh * L_SEQ * (HD/2);
    const __half*  __restrict__ Kp = g_K + (size_t)bh * HD * L_SEQ;
    const __half*  __restrict__ Vp = (const __half*)(g_V + (size_t)bh * L_SEQ * (HD/2));

    uint32_t ks_base = (uint32_t)__cvta_generic_to_shared(&Ks[0][0]);
    uint32_t vs_base = (uint32_t)__cvta_generic_to_shared(&Vs[0][0]);

    // Q A-fragments from gmem (reused for all key tiles)
    uint32_t aq[2][4];
    #pragma unroll
    for (int kc = 0; kc < 2; kc++) {
        aq[kc][0] = *(const uint32_t*)&Qh[(size_t)(q0 + m0 + gid    ) * (HD/2) + kc * 8 + tig    ];
        aq[kc][1] = *(const uint32_t*)&Qh[(size_t)(q0 + m0 + gid + 8) * (HD/2) + kc * 8 + tig    ];
        aq[kc][2] = *(const uint32_t*)&Qh[(size_t)(q0 + m0 + gid    ) * (HD/2) + kc * 8 + tig + 4];
        aq[kc][3] = *(const uint32_t*)&Qh[(size_t)(q0 + m0 + gid + 8) * (HD/2) + kc * 8 + tig + 4];
    }

    float m_lo = -1e30f, m_hi = -1e30f, l_lo = 0.f, l_hi = 0.f;
    float oc[4][4];
    #pragma unroll
    for (int nf = 0; nf < 4; nf++)
        #pragma unroll
        for (int j = 0; j < 4; j++) oc[nf][j] = 0.f;

    for (int kt = 0; kt < L_SEQ; kt += KT) {
        __syncthreads();
        // fill Ks[d][key]: 32 rows x 256B = 512 uint4 chunks
        #pragma unroll
        for (int i = tid; i < 512; i += 128) {
            int d = i >> 4, c = i & 15;
            *(uint4*)&Ks[d][c * 8] = *((const uint4*)(Kp + (size_t)d * L_SEQ + kt) + c);
        }
        // fill Vs[key][d]: 128 rows x 64B = 512 uint4 chunks
        #pragma unroll
        for (int i = tid; i < 512; i += 128) {
            int key = i >> 2, c = i & 3;
            *(uint4*)&Vs[key][c * 8] = *((const uint4*)(Vp + (size_t)(kt + key) * HD) + c);
        }
        __syncthreads();

        // ---- S = Q K^T  (logits already in log2 domain via Q scale) ----
        float sc[16][4];
        #pragma unroll
        for (int nn = 0; nn < 16; nn++) {
            sc[nn][0] = sc[nn][1] = sc[nn][2] = sc[nn][3] = 0.f;
            uint32_t b[4];
            ldsm4t(b, ks_base + lane * 272 + nn * 16);
            mma_f16(sc[nn], aq[0][0], aq[0][1], aq[0][2], aq[0][3], b[0], b[1]);
            mma_f16(sc[nn], aq[1][0], aq[1][1], aq[1][2], aq[1][3], b[2], b[3]);
        }

        // ---- online softmax (exp2 domain) ----
        float mx_lo = -1e30f, mx_hi = -1e30f;
        #pragma unroll
        for (int nn = 0; nn < 16; nn++) {
            mx_lo = fmaxf(mx_lo, fmaxf(sc[nn][0], sc[nn][1]));
            mx_hi = fmaxf(mx_hi, fmaxf(sc[nn][2], sc[nn][3]));
        }
        mx_lo = fmaxf(mx_lo, __shfl_xor_sync(0xffffffffu, mx_lo, 1));
        mx_lo = fmaxf(mx_lo, __shfl_xor_sync(0xffffffffu, mx_lo, 2));
        mx_hi = fmaxf(mx_hi, __shfl_xor_sync(0xffffffffu, mx_hi, 1));
        mx_hi = fmaxf(mx_hi, __shfl_xor_sync(0xffffffffu, mx_hi, 2));

        float mn_lo = fmaxf(m_lo, mx_lo), mn_hi = fmaxf(m_hi, mx_hi);
        float al_lo = ex2(m_lo - mn_lo), al_hi = ex2(m_hi - mn_hi);
        m_lo = mn_lo; m_hi = mn_hi;

        float sum_lo = 0.f, sum_hi = 0.f;
        #pragma unroll
        for (int nn = 0; nn < 16; nn++) {
            float p0 = ex2(sc[nn][0] - mn_lo);
            float p1 = ex2(sc[nn][1] - mn_lo);
            float p2 = ex2(sc[nn][2] - mn_hi);
            float p3 = ex2(sc[nn][3] - mn_hi);
            sum_lo += p0 + p1;  sum_hi += p2 + p3;
            sc[nn][0] = p0; sc[nn][1] = p1; sc[nn][2] = p2; sc[nn][3] = p3;
        }
        sum_lo += __shfl_xor_sync(0xffffffffu, sum_lo, 1);
        sum_lo += __shfl_xor_sync(0xffffffffu, sum_lo, 2);
        sum_hi += __shfl_xor_sync(0xffffffffu, sum_hi, 1);
        sum_hi += __shfl_xor_sync(0xffffffffu, sum_hi, 2);
        l_lo = l_lo * al_lo + sum_lo;
        l_hi = l_hi * al_hi + sum_hi;

        #pragma unroll
        for (int nf = 0; nf < 4; nf++) {
            oc[nf][0] *= al_lo; oc[nf][1] *= al_lo;
            oc[nf][2] *= al_hi; oc[nf][3] *= al_hi;
        }

        // ---- O += P V ----
        #pragma unroll
        for (int kg = 0; kg < 4; kg++) {          // 32 keys per group
            uint32_t pA0 = pack2(sc[4*kg    ][0], sc[4*kg    ][1]);
            uint32_t pA1 = pack2(sc[4*kg    ][2], sc[4*kg    ][3]);
            uint32_t pA2 = pack2(sc[4*kg + 1][0], sc[4*kg + 1][1]);
            uint32_t pA3 = pack2(sc[4*kg + 1][2], sc[4*kg + 1][3]);
            uint32_t pB0 = pack2(sc[4*kg + 2][0], sc[4*kg + 2][1]);
            uint32_t pB1 = pack2(sc[4*kg + 2][2], sc[4*kg + 2][3]);
            uint32_t pB2 = pack2(sc[4*kg + 3][0], sc[4*kg + 3][1]);
            uint32_t pB3 = pack2(sc[4*kg + 3][2], sc[4*kg + 3][3]);
            #pragma unroll
            for (int nf = 0; nf < 4; nf++) {
                uint32_t v[4];
                ldsm4t(v, vs_base + (kg * 32 + lane) * 80 + nf * 16);
                mma_f16(oc[nf], pA0, pA1, pA2, pA3, v[0], v[1]);
                mma_f16(oc[nf], pB0, pB1, pB2, pB3, v[2], v[3]);
            }
        }
    }

    // ---- normalize + store to g_AO [l][b][e/2] ----
    float inv_lo = 1.f / l_lo, inv_hi = 1.f / l_hi;
    int b = bh >> 3, h = bh & 7;
    int r_lo = q0 + m0 + gid, r_hi = r_lo + 8;
    #pragma unroll
    for (int nf = 0; nf < 4; nf++) {
        int c2 = h * 16 + nf * 4 + tig;
        g_AO[((size_t)r_lo * BATCH + b) * (EMB/2) + c2] =
            __floats2half2_rn(oc[nf][0] * inv_lo, oc[nf][1] * inv_lo);
        g_AO[((size_t)r_hi * BATCH + b) * (EMB/2) + c2] =
            __floats2half2_rn(oc[nf][2] * inv_hi, oc[nf][3] * inv_hi);
    }
}

// ---------------------------------------------------------------------------
extern "C" void kernel_launch(void* const* d_in, const int* in_sizes, int n_in,
                              void* d_out, int out_size)
{
    const float* query = (const float*)d_in[0];
    const float* key_  = (const float*)d_in[1];
    const float* value = (const float*)d_in[2];
    const float* Wq = (const float*)d_in[3];
    const float* bq = (const float*)d_in[4];
    const float* Wk = (const float*)d_in[5];
    const float* bk = (const float*)d_in[6];
    const float* Wv = (const float*)d_in[7];
    const float* bv = (const float*)d_in[8];
    const float* Wp = (const float*)d_in[9];
    const float* bp = (const float*)d_in[10];
    float* out = (float*)d_out;

    // fused Q/K/V projections: grid.z selects which
    dim3 gridQKV(EMB / 64, NROWS / 64, 3);   // (4, 64, 3)
    proj_kernel<0><<<gridQKV, 128>>>(query, key_, value,
                                     Wq, Wk, Wv, bq, bk, bv, nullptr);

    dim3 gridA(L_SEQ / 64, BATCH * NH);      // (32, 16)
    attn_kernel<<<gridA, 128>>>();

    dim3 gridP(EMB / 64, NROWS / 64, 1);
    proj_kernel<1><<<gridP, 128>>>(nullptr, nullptr, nullptr,
                                   Wp, nullptr, nullptr, bp, nullptr, nullptr, out);
}

// round 6
// speedup vs baseline: 5.8083x; 1.2105x over previous
#include <cuda_runtime.h>
#include <cuda_fp16.h>
#include <cstdint>

#define L_SEQ 2048
#define BATCH 2
#define EMB   256
#define NH    8
#define HD    32
#define NROWS (L_SEQ*BATCH)   // 4096
#define KT    128             // attention key tile
// SCALE * log2(e): softmax done in exp2 domain
#define SCALE_LOG2E 0.25500927171408637f

// Scratch (allocation-free), fp16:
__device__ __half2 g_Xh[3*NROWS*(EMB/2)];   // fp16 copies of query/key_/value
__device__ __half2 g_Wh[4*EMB*(EMB/2)];     // fp16 copies of Wq/Wk/Wv/Wp
__device__ __half2 g_Q[BATCH*NH*L_SEQ*(HD/2)];   // [b][h][l][d/2], pre-scaled
__device__ __half  g_K[BATCH*NH*HD*L_SEQ];       // [b][h][d][l]
__device__ __half2 g_V[BATCH*NH*L_SEQ*(HD/2)];   // [b][h][l][d/2]
__device__ __half2 g_AO[NROWS*(EMB/2)];          // [l][b][e/2]

// ---------------------------------------------------------------------------
__device__ __forceinline__ uint32_t pack2(float x, float y) {
    __half2 h = __floats2half2_rn(x, y);
    return *reinterpret_cast<uint32_t*>(&h);
}
__device__ __forceinline__ float ex2(float x) {
    float y; asm("ex2.approx.ftz.f32 %0, %1;" : "=f"(y) : "f"(x)); return y;
}
__device__ __forceinline__ void mma_f16(float c[4],
    uint32_t a0, uint32_t a1, uint32_t a2, uint32_t a3,
    uint32_t b0, uint32_t b1)
{
    asm volatile(
        "mma.sync.aligned.m16n8k16.row.col.f32.f16.f16.f32 "
        "{%0,%1,%2,%3},{%4,%5,%6,%7},{%8,%9},{%0,%1,%2,%3};"
        : "+f"(c[0]), "+f"(c[1]), "+f"(c[2]), "+f"(c[3])
        : "r"(a0), "r"(a1), "r"(a2), "r"(a3), "r"(b0), "r"(b1));
}
__device__ __forceinline__ void ldsm4(uint32_t r[4], uint32_t addr) {
    asm volatile("ldmatrix.sync.aligned.m8n8.x4.shared.b16 {%0,%1,%2,%3},[%4];"
        : "=r"(r[0]), "=r"(r[1]), "=r"(r[2]), "=r"(r[3]) : "r"(addr));
}
__device__ __forceinline__ void ldsm4t(uint32_t r[4], uint32_t addr) {
    asm volatile("ldmatrix.sync.aligned.m8n8.x4.trans.shared.b16 {%0,%1,%2,%3},[%4];"
        : "=r"(r[0]), "=r"(r[1]), "=r"(r[2]), "=r"(r[3]) : "r"(addr));
}
__device__ __forceinline__ void cpa16(uint32_t dst, const void* src) {
    asm volatile("cp.async.ca.shared.global [%0], [%1], 16;" :: "r"(dst), "l"(src));
}
__device__ __forceinline__ void cp_commit() {
    asm volatile("cp.async.commit_group;");
}
template<int N> __device__ __forceinline__ void cp_wait() {
    asm volatile("cp.async.wait_group %0;" :: "n"(N));
}

// ---------------------------------------------------------------------------
// fp32 -> fp16 conversion of X (3 tensors) and W (4 tensors)
// grid: (2048, 7), 256 thr. y<3: X (524288 half2); y>=3: W (32768 half2)
// ---------------------------------------------------------------------------
__global__ __launch_bounds__(256) void convert_kernel(
    const float* __restrict__ q, const float* __restrict__ k, const float* __restrict__ v,
    const float* __restrict__ wq, const float* __restrict__ wk,
    const float* __restrict__ wv, const float* __restrict__ wp)
{
    int y = blockIdx.y;
    int i = blockIdx.x * 256 + threadIdx.x;
    if (y < 3) {
        const float* src = (y == 0) ? q : (y == 1) ? k : v;
        float2 xv = *(const float2*)&src[2 * (size_t)i];
        g_Xh[(size_t)y * (NROWS*(EMB/2)) + i] = __floats2half2_rn(xv.x, xv.y);
    } else {
        if (i >= EMB*(EMB/2)) return;
        const float* src = (y == 3) ? wq : (y == 4) ? wk : (y == 5) ? wv : wp;
        float2 xv = *(const float2*)&src[2 * (size_t)i];
        g_Wh[(size_t)(y - 3) * (EMB*(EMB/2)) + i] = __floats2half2_rn(xv.x, xv.y);
    }
}

// ---------------------------------------------------------------------------
// Projection GEMM: C[4096,256] = X @ W + bias, fp16 mma + ldmatrix,
// cp.async 2-stage pipeline. CTA: 128 thr, tile 64x64, k-step 32.
// SRC_AO: 0 = g_Xh[z] -> g_Q/g_K/g_V, 1 = g_AO -> Cout fp32 (W = Wp)
// ---------------------------------------------------------------------------
template<int SRC_AO>
__global__ __launch_bounds__(128) void proj_kernel(
    const float* __restrict__ B0, const float* __restrict__ B1,
    const float* __restrict__ B2, float* __restrict__ Cout)
{
    __shared__ __align__(16) __half Xs[2][64][40];   // stage 5120B (128B-mult)
    __shared__ __align__(16) __half Ws[2][32][72];   // stage 4608B

    int z = blockIdx.z;
    const __half2* __restrict__ Xsrc =
        SRC_AO ? g_AO : g_Xh + (size_t)z * (NROWS*(EMB/2));
    const __half2* __restrict__ Wsrc =
        g_Wh + (size_t)(SRC_AO ? 3 : z) * (EMB*(EMB/2));
    const float* __restrict__ bias = (z == 0) ? B0 : (z == 1) ? B1 : B2;
    int dst = SRC_AO ? 0 : (z + 1);

    int tid  = threadIdx.x;
    int lane = tid & 31, warp = tid >> 5;
    int gid  = lane >> 2, tig = lane & 3;
    int m0   = warp * 16;
    int rowBase = blockIdx.y * 64;
    int colBase = blockIdx.x * 64;

    uint32_t xs_base = (uint32_t)__cvta_generic_to_shared(&Xs[0][0][0]);
    uint32_t ws_base = (uint32_t)__cvta_generic_to_shared(&Ws[0][0][0]);

    // stage fill: X 64 rows x 4 chunks, W 32 rows x 8 chunks (16B each)
    auto fill = [&](int s, int k0) {
        uint32_t xb = xs_base + s * 5120;
        uint32_t wb = ws_base + s * 4608;
        #pragma unroll
        for (int i = tid; i < 256; i += 128) {
            int r = i >> 2, c = i & 3;
            cpa16(xb + r * 80 + c * 16,
                  Xsrc + (size_t)(rowBase + r) * (EMB/2) + (k0 >> 1) + c * 4);
        }
        #pragma unroll
        for (int i = tid; i < 256; i += 128) {
            int r = i >> 3, c = i & 7;
            cpa16(wb + r * 144 + c * 16,
                  Wsrc + (size_t)(k0 + r) * (EMB/2) + (colBase >> 1) + c * 4);
        }
    };

    float cc[8][4];
    #pragma unroll
    for (int nn = 0; nn < 8; nn++)
        #pragma unroll
        for (int j = 0; j < 4; j++) cc[nn][j] = 0.f;

    fill(0, 0); cp_commit();

    for (int it = 0; it < 8; it++) {
        if (it < 7) { fill((it + 1) & 1, (it + 1) * 32); cp_commit(); }
        if (it < 7) cp_wait<1>(); else cp_wait<0>();
        __syncthreads();

        uint32_t xb = xs_base + (it & 1) * 5120;
        uint32_t wb = ws_base + (it & 1) * 4608;

        uint32_t a[2][4];
        #pragma unroll
        for (int kc = 0; kc < 2; kc++) {
            int m = lane >> 3;
            int row = m0 + (m & 1) * 8 + (lane & 7);
            int koff = kc * 16 + (m >> 1) * 8;
            ldsm4(a[kc], xb + row * 80 + koff * 2);
        }
        #pragma unroll
        for (int nn = 0; nn < 8; nn++) {
            uint32_t b[4];
            ldsm4t(b, wb + lane * 144 + nn * 16);
            mma_f16(cc[nn], a[0][0], a[0][1], a[0][2], a[0][3], b[0], b[1]);
            mma_f16(cc[nn], a[1][0], a[1][1], a[1][2], a[1][3], b[2], b[3]);
        }
        __syncthreads();
    }

    // epilogue
    int r_lo = rowBase + m0 + gid;
    int r_hi = r_lo + 8;
    #pragma unroll
    for (int nn = 0; nn < 8; nn++) {
        int c0 = colBase + nn * 8 + 2 * tig;
        float bv0 = bias[c0], bv1 = bias[c0 + 1];
        float v00 = cc[nn][0] + bv0, v01 = cc[nn][1] + bv1;   // row r_lo
        float v10 = cc[nn][2] + bv0, v11 = cc[nn][3] + bv1;   // row r_hi
        if (dst == 0) {
            *(float2*)&Cout[(size_t)r_lo * EMB + c0] = make_float2(v00, v01);
            *(float2*)&Cout[(size_t)r_hi * EMB + c0] = make_float2(v10, v11);
        } else {
            int h = (c0 >> 5) & 7, d = c0 & 31;
            int l0 = r_lo >> 1, b0i = r_lo & 1;     // row = l*B + b
            int l1 = r_hi >> 1, b1i = r_hi & 1;
            int bh0 = b0i * NH + h, bh1 = b1i * NH + h;
            if (dst == 1) {
                g_Q[((size_t)bh0 * L_SEQ + l0) * (HD/2) + (d >> 1)] =
                    __floats2half2_rn(v00 * SCALE_LOG2E, v01 * SCALE_LOG2E);
                g_Q[((size_t)bh1 * L_SEQ + l1) * (HD/2) + (d >> 1)] =
                    __floats2half2_rn(v10 * SCALE_LOG2E, v11 * SCALE_LOG2E);
            } else if (dst == 2) {
                g_K[((size_t)bh0 * HD + d    ) * L_SEQ + l0] = __float2half_rn(v00);
                g_K[((size_t)bh0 * HD + d + 1) * L_SEQ + l0] = __float2half_rn(v01);
                g_K[((size_t)bh1 * HD + d    ) * L_SEQ + l1] = __float2half_rn(v10);
                g_K[((size_t)bh1 * HD + d + 1) * L_SEQ + l1] = __float2half_rn(v11);
            } else {
                g_V[((size_t)bh0 * L_SEQ + l0) * (HD/2) + (d >> 1)] = __floats2half2_rn(v00, v01);
                g_V[((size_t)bh1 * L_SEQ + l1) * (HD/2) + (d >> 1)] = __floats2half2_rn(v10, v11);
            }
        }
    }
}

// ---------------------------------------------------------------------------
// Flash attention: CTA = (b,h) x 64-query tile, 4 warps x 16 rows,
// 128-key tiles with 2-stage cp.async pipeline. Softmax in exp2 domain.
// ---------------------------------------------------------------------------
__global__ __launch_bounds__(128) void attn_kernel()
{
    __shared__ __align__(16) __half Ks[2][32][136];   // stage 8704B (128B-mult)
    __shared__ __align__(16) __half Vs[2][128][40];   // stage 10240B

    int bh = blockIdx.y;
    int q0 = blockIdx.x * 64;
    int tid  = threadIdx.x;
    int lane = tid & 31, warp = tid >> 5;
    int gid  = lane >> 2, tig = lane & 3;
    int m0   = warp * 16;

    const __half2* __restrict__ Qh = g_Q + (size_t)bh * L_SEQ * (HD/2);
    const __half*  __restrict__ Kp = g_K + (size_t)bh * HD * L_SEQ;
    const __half*  __restrict__ Vp = (const __half*)(g_V + (size_t)bh * L_SEQ * (HD/2));

    uint32_t ks_base = (uint32_t)__cvta_generic_to_shared(&Ks[0][0][0]);
    uint32_t vs_base = (uint32_t)__cvta_generic_to_shared(&Vs[0][0][0]);

    auto fill = [&](int s, int kt) {
        uint32_t kb = ks_base + s * 8704;
        uint32_t vb = vs_base + s * 10240;
        #pragma unroll
        for (int i = tid; i < 512; i += 128) {
            int d = i >> 4, c = i & 15;
            cpa16(kb + d * 272 + c * 16, Kp + (size_t)d * L_SEQ + kt + c * 8);
        }
        #pragma unroll
        for (int i = tid; i < 512; i += 128) {
            int key = i >> 2, c = i & 3;
            cpa16(vb + key * 80 + c * 16, Vp + (size_t)(kt + key) * HD + c * 8);
        }
    };

    // Q A-fragments from gmem (reused for all key tiles)
    uint32_t aq[2][4];
    #pragma unroll
    for (int kc = 0; kc < 2; kc++) {
        aq[kc][0] = *(const uint32_t*)&Qh[(size_t)(q0 + m0 + gid    ) * (HD/2) + kc * 8 + tig    ];
        aq[kc][1] = *(const uint32_t*)&Qh[(size_t)(q0 + m0 + gid + 8) * (HD/2) + kc * 8 + tig    ];
        aq[kc][2] = *(const uint32_t*)&Qh[(size_t)(q0 + m0 + gid    ) * (HD/2) + kc * 8 + tig + 4];
        aq[kc][3] = *(const uint32_t*)&Qh[(size_t)(q0 + m0 + gid + 8) * (HD/2) + kc * 8 + tig + 4];
    }

    float m_lo = -1e30f, m_hi = -1e30f, l_lo = 0.f, l_hi = 0.f;
    float oc[4][4];
    #pragma unroll
    for (int nf = 0; nf < 4; nf++)
        #pragma unroll
        for (int j = 0; j < 4; j++) oc[nf][j] = 0.f;

    fill(0, 0); cp_commit();

    for (int it = 0; it < L_SEQ / KT; it++) {
        if (it < L_SEQ / KT - 1) { fill((it + 1) & 1, (it + 1) * KT); cp_commit(); }
        if (it < L_SEQ / KT - 1) cp_wait<1>(); else cp_wait<0>();
        __syncthreads();

        uint32_t kb = ks_base + (it & 1) * 8704;
        uint32_t vb = vs_base + (it & 1) * 10240;

        // ---- S = Q K^T (logits in log2 domain via Q scale) ----
        float sc[16][4];
        #pragma unroll
        for (int nn = 0; nn < 16; nn++) {
            sc[nn][0] = sc[nn][1] = sc[nn][2] = sc[nn][3] = 0.f;
            uint32_t b[4];
            ldsm4t(b, kb + lane * 272 + nn * 16);
            mma_f16(sc[nn], aq[0][0], aq[0][1], aq[0][2], aq[0][3], b[0], b[1]);
            mma_f16(sc[nn], aq[1][0], aq[1][1], aq[1][2], aq[1][3], b[2], b[3]);
        }

        // ---- online softmax (exp2 domain) ----
        float mx_lo = -1e30f, mx_hi = -1e30f;
        #pragma unroll
        for (int nn = 0; nn < 16; nn++) {
            mx_lo = fmaxf(mx_lo, fmaxf(sc[nn][0], sc[nn][1]));
            mx_hi = fmaxf(mx_hi, fmaxf(sc[nn][2], sc[nn][3]));
        }
        mx_lo = fmaxf(mx_lo, __shfl_xor_sync(0xffffffffu, mx_lo, 1));
        mx_lo = fmaxf(mx_lo, __shfl_xor_sync(0xffffffffu, mx_lo, 2));
        mx_hi = fmaxf(mx_hi, __shfl_xor_sync(0xffffffffu, mx_hi, 1));
        mx_hi = fmaxf(mx_hi, __shfl_xor_sync(0xffffffffu, mx_hi, 2));

        float mn_lo = fmaxf(m_lo, mx_lo), mn_hi = fmaxf(m_hi, mx_hi);
        float al_lo = ex2(m_lo - mn_lo), al_hi = ex2(m_hi - mn_hi);
        m_lo = mn_lo; m_hi = mn_hi;

        float sum_lo = 0.f, sum_hi = 0.f;
        #pragma unroll
        for (int nn = 0; nn < 16; nn++) {
            float p0 = ex2(sc[nn][0] - mn_lo);
            float p1 = ex2(sc[nn][1] - mn_lo);
            float p2 = ex2(sc[nn][2] - mn_hi);
            float p3 = ex2(sc[nn][3] - mn_hi);
            sum_lo += p0 + p1;  sum_hi += p2 + p3;
            sc[nn][0] = p0; sc[nn][1] = p1; sc[nn][2] = p2; sc[nn][3] = p3;
        }
        sum_lo += __shfl_xor_sync(0xffffffffu, sum_lo, 1);
        sum_lo += __shfl_xor_sync(0xffffffffu, sum_lo, 2);
        sum_hi += __shfl_xor_sync(0xffffffffu, sum_hi, 1);
        sum_hi += __shfl_xor_sync(0xffffffffu, sum_hi, 2);
        l_lo = l_lo * al_lo + sum_lo;
        l_hi = l_hi * al_hi + sum_hi;

        #pragma unroll
        for (int nf = 0; nf < 4; nf++) {
            oc[nf][0] *= al_lo; oc[nf][1] *= al_lo;
            oc[nf][2] *= al_hi; oc[nf][3] *= al_hi;
        }

        // ---- O += P V ----
        #pragma unroll
        for (int kg = 0; kg < 4; kg++) {
            uint32_t pA0 = pack2(sc[4*kg    ][0], sc[4*kg    ][1]);
            uint32_t pA1 = pack2(sc[4*kg    ][2], sc[4*kg    ][3]);
            uint32_t pA2 = pack2(sc[4*kg + 1][0], sc[4*kg + 1][1]);
            uint32_t pA3 = pack2(sc[4*kg + 1][2], sc[4*kg + 1][3]);
            uint32_t pB0 = pack2(sc[4*kg + 2][0], sc[4*kg + 2][1]);
            uint32_t pB1 = pack2(sc[4*kg + 2][2], sc[4*kg + 2][3]);
            uint32_t pB2 = pack2(sc[4*kg + 3][0], sc[4*kg + 3][1]);
            uint32_t pB3 = pack2(sc[4*kg + 3][2], sc[4*kg + 3][3]);
            #pragma unroll
            for (int nf = 0; nf < 4; nf++) {
                uint32_t v[4];
                ldsm4t(v, vb + (kg * 32 + lane) * 80 + nf * 16);
                mma_f16(oc[nf], pA0, pA1, pA2, pA3, v[0], v[1]);
                mma_f16(oc[nf], pB0, pB1, pB2, pB3, v[2], v[3]);
            }
        }
        __syncthreads();
    }

    // ---- normalize + store to g_AO [l][b][e/2] ----
    float inv_lo = 1.f / l_lo, inv_hi = 1.f / l_hi;
    int b = bh >> 3, h = bh & 7;
    int r_lo = q0 + m0 + gid, r_hi = r_lo + 8;
    #pragma unroll
    for (int nf = 0; nf < 4; nf++) {
        int c2 = h * 16 + nf * 4 + tig;
        g_AO[((size_t)r_lo * BATCH + b) * (EMB/2) + c2] =
            __floats2half2_rn(oc[nf][0] * inv_lo, oc[nf][1] * inv_lo);
        g_AO[((size_t)r_hi * BATCH + b) * (EMB/2) + c2] =
            __floats2half2_rn(oc[nf][2] * inv_hi, oc[nf][3] * inv_hi);
    }
}

// ---------------------------------------------------------------------------
extern "C" void kernel_launch(void* const* d_in, const int* in_sizes, int n_in,
                              void* d_out, int out_size)
{
    const float* query = (const float*)d_in[0];
    const float* key_  = (const float*)d_in[1];
    const float* value = (const float*)d_in[2];
    const float* Wq = (const float*)d_in[3];
    const float* bq = (const float*)d_in[4];
    const float* Wk = (const float*)d_in[5];
    const float* bk = (const float*)d_in[6];
    const float* Wv = (const float*)d_in[7];
    const float* bv = (const float*)d_in[8];
    const float* Wp = (const float*)d_in[9];
    const float* bp = (const float*)d_in[10];
    float* out = (float*)d_out;

    dim3 gridC((NROWS * (EMB/2)) / 256, 7);   // (2048, 7)
    convert_kernel<<<gridC, 256>>>(query, key_, value, Wq, Wk, Wv, Wp);

    dim3 gridQKV(EMB / 64, NROWS / 64, 3);    // (4, 64, 3)
    proj_kernel<0><<<gridQKV, 128>>>(bq, bk, bv, nullptr);

    dim3 gridA(L_SEQ / 64, BATCH * NH);       // (32, 16)
    attn_kernel<<<gridA, 128>>>();

    dim3 gridP(EMB / 64, NROWS / 64, 1);
    proj_kernel<1><<<gridP, 128>>>(bp, nullptr, nullptr, out);
}